// round 7
// baseline (speedup 1.0000x reference)
#include <cuda_runtime.h>
#include <math.h>

#define BB   128
#define NS   128
#define NQ   512
#define DIN  256
#define DOUT 64

#define MU_N  ((long long)BB * NQ * DOUT)            // 4,194,304
#define SIG_N ((long long)BB * NQ * DOUT * DOUT)     // 134,217,728

// ---------------- scratch (floats) ----------------
#define OFF_SP     0LL
#define OFF_MPN    65536LL
#define OFF_SINV   81920LL
#define OFF_W      8470528LL
#define OFF_V      16859136LL
#define OFF_X      18956288LL
#define OFF_SC     21053440LL
#define OFF_RHS    23150592LL
#define OFF_T      25247744LL
#define OFF_M      27344896LL
#define OFF_SPREAD 29442048LL
#define BUF_TOTAL  29507584LL

__device__ float  g_buf[BUF_TOTAL];
__device__ double g_nll_acc;

// ======================================================================
// Generic batched SGEMM, 128x(BN) CTA tile, 256 threads, (8)x(BN/16) reg tile.
// C[b] = alpha * op(A[b]) @ op(B[b]) + (Dd ? Dd[b] : 0)
// tA==0: A is MxK row-major;  tA==1: A stored KxM (op(A)=A_stored^T)
// tB==0: B is KxN row-major;  tB==1: B stored NxK (op(B)=B_stored^T)
// If SPREPI: nothing is stored; instead rowsum(opA@opB elementwise^2) is
// atomically added into spread[b*M + row]. (alpha ignored, assumed 1.)
// Requires M % BM == 0, N % BN == 0, K % 16 == 0, pointers 16B aligned.
// ======================================================================
template<int BM, int BN, bool SPREPI>
__global__ void __launch_bounds__(256, 2) gemm_k(
    int M, int N, int K,
    const float* __restrict__ A, int lda, long long sA, int tA,
    const float* __restrict__ B, int ldb, long long sB, int tB,
    const float* __restrict__ Dd, int ldd, long long sD,
    float alpha,
    float* __restrict__ C, int ldc, long long sC,
    float* __restrict__ spread)
{
    constexpr int TM = BM / 16;       // 8
    constexpr int TN = BN / 16;       // 8 or 4
    constexpr int LAS = BM + 4;
    constexpr int LBS = BN + 4;
    __shared__ float As[16][LAS];
    __shared__ float Bs[16][LBS];

    const int b  = blockIdx.z;
    const float* Ab = A + (long long)b * sA;
    const float* Bb = B + (long long)b * sB;

    const int m0 = blockIdx.y * BM;
    const int n0 = blockIdx.x * BN;
    const int tid = threadIdx.x;
    const int tx = tid & 15;
    const int ty = tid >> 4;

    float acc[TM][TN];
#pragma unroll
    for (int i = 0; i < TM; i++)
#pragma unroll
        for (int j = 0; j < TN; j++) acc[i][j] = 0.f;

    for (int k0 = 0; k0 < K; k0 += 16) {
        // ---- stage A tile: As[k][m] ----
        if (tA == 0) {
#pragma unroll
            for (int p = tid; p < BM * 4; p += 256) {
                int m  = p >> 2;
                int kq = (p & 3) * 4;
                float4 v = *(const float4*)(Ab + (long long)(m0 + m) * lda + k0 + kq);
                As[kq + 0][m] = v.x; As[kq + 1][m] = v.y;
                As[kq + 2][m] = v.z; As[kq + 3][m] = v.w;
            }
        } else {
#pragma unroll
            for (int p = tid; p < BM * 4; p += 256) {
                int k  = p / (BM / 4);
                int mq = (p % (BM / 4)) * 4;
                *(float4*)&As[k][mq] = *(const float4*)(Ab + (long long)(k0 + k) * lda + m0 + mq);
            }
        }
        // ---- stage B tile: Bs[k][n] ----
        if (tB == 0) {
#pragma unroll
            for (int p = tid; p < BN * 4; p += 256) {
                int k  = p / (BN / 4);
                int nq = (p % (BN / 4)) * 4;
                *(float4*)&Bs[k][nq] = *(const float4*)(Bb + (long long)(k0 + k) * ldb + n0 + nq);
            }
        } else {
#pragma unroll
            for (int p = tid; p < BN * 4; p += 256) {
                int n  = p >> 2;
                int kq = (p & 3) * 4;
                float4 v = *(const float4*)(Bb + (long long)(n0 + n) * ldb + k0 + kq);
                Bs[kq + 0][n] = v.x; Bs[kq + 1][n] = v.y;
                Bs[kq + 2][n] = v.z; Bs[kq + 3][n] = v.w;
            }
        }
        __syncthreads();

#pragma unroll
        for (int k = 0; k < 16; k++) {
            float a[TM], bv[TN];
#pragma unroll
            for (int g = 0; g < TM / 4; g++)
                *(float4*)&a[g * 4] = *(const float4*)&As[k][g * 64 + ty * 4];
#pragma unroll
            for (int g = 0; g < TN / 4; g++)
                *(float4*)&bv[g * 4] = *(const float4*)&Bs[k][g * 64 + tx * 4];
#pragma unroll
            for (int i = 0; i < TM; i++)
#pragma unroll
                for (int j = 0; j < TN; j++)
                    acc[i][j] += a[i] * bv[j];
        }
        __syncthreads();
    }

    if (!SPREPI) {
        float* Cb = C + (long long)b * sC;
#pragma unroll
        for (int i = 0; i < TM; i++) {
            int m = m0 + (i / 4) * 64 + ty * 4 + (i & 3);
#pragma unroll
            for (int gj = 0; gj < TN / 4; gj++) {
                int n = n0 + gj * 64 + tx * 4;
                float4 o;
                o.x = alpha * acc[i][gj * 4 + 0];
                o.y = alpha * acc[i][gj * 4 + 1];
                o.z = alpha * acc[i][gj * 4 + 2];
                o.w = alpha * acc[i][gj * 4 + 3];
                if (Dd) {
                    float4 d = *(const float4*)(Dd + (long long)b * sD + (long long)m * ldd + n);
                    o.x += d.x; o.y += d.y; o.z += d.z; o.w += d.w;
                }
                *(float4*)(Cb + (long long)m * ldc + n) = o;
            }
        }
    } else {
        // rowsum of squares -> spread[b*M + row]
#pragma unroll
        for (int i = 0; i < TM; i++) {
            float s = 0.f;
#pragma unroll
            for (int j = 0; j < TN; j++) s += acc[i][j] * acc[i][j];
            // reduce over the 16 threads sharing the same ty (same rows)
            s += __shfl_xor_sync(0xFFFFFFFFu, s, 1);
            s += __shfl_xor_sync(0xFFFFFFFFu, s, 2);
            s += __shfl_xor_sync(0xFFFFFFFFu, s, 4);
            s += __shfl_xor_sync(0xFFFFFFFFu, s, 8);
            if (tx == 0) {
                int m = m0 + (i / 4) * 64 + ty * 4 + (i & 3);
                atomicAdd(&spread[(long long)b * M + m], s);
            }
        }
    }
}

// ======================================================================
// Per-CTA smem Cholesky + triangular inverse (n=128), double accumulation.
// Output: Linv (lower), A^{-1} = Linv^T Linv. Written with ldout/strideOut.
// ======================================================================
__global__ void chol_linv_kernel(const float* __restrict__ in, int ldin, long long strideIn,
                                 float* __restrict__ Lout, int ldout, long long strideOut)
{
    extern __shared__ float sh[];
    float* sL  = sh;                 // [128][129]
    float* sX  = sh + 128 * 129;     // [128][129]
    float* rd  = sh + 2 * 128 * 129; // [128]
    float* sdi = rd + 128;           // [1]
#define SL(i,k) sL[(i) * 129 + (k)]
#define SX(i,k) sX[(i) * 129 + (k)]

    int b   = blockIdx.x;
    int tid = threadIdx.x;          // 0..127
    const float* A = in + (long long)b * strideIn;
    float* out = Lout + (long long)b * strideOut;

    for (int idx = tid; idx < 128 * 128; idx += 128) {
        int r = idx >> 7, c = idx & 127;
        SL(r, c) = A[(long long)r * ldin + c];
    }
    __syncthreads();

    // left-looking Cholesky (lower), double accumulation
    for (int j = 0; j < 128; j++) {
        float t = 0.f;
        if (tid >= j) {
            double a0 = 0.0, a1 = 0.0, a2 = 0.0, a3 = 0.0;
            int k = 0;
            for (; k + 3 < j; k += 4) {
                a0 += (double)SL(tid, k)     * (double)SL(j, k);
                a1 += (double)SL(tid, k + 1) * (double)SL(j, k + 1);
                a2 += (double)SL(tid, k + 2) * (double)SL(j, k + 2);
                a3 += (double)SL(tid, k + 3) * (double)SL(j, k + 3);
            }
            for (; k < j; k++) a0 += (double)SL(tid, k) * (double)SL(j, k);
            t = (float)((double)SL(tid, j) - ((a0 + a1) + (a2 + a3)));
        }
        if (tid == j) {
            float d = sqrtf(t);
            SL(j, j) = d;
            sdi[0] = 1.f / d;
        }
        __syncthreads();
        if (tid > j) SL(tid, j) = t * sdi[0];
        __syncthreads();
    }

    rd[tid] = 1.f / SL(tid, tid);
    __syncthreads();

    // column-parallel triangular inverse: sX = L^{-1}, double accumulation
    {
        int c = tid;
        for (int i = 0; i < c; i++) SX(i, c) = 0.f;
        SX(c, c) = rd[c];
        for (int i = c + 1; i < 128; i++) {
            double a0 = 0.0, a1 = 0.0, a2 = 0.0, a3 = 0.0;
            int k = c;
            for (; k + 3 < i; k += 4) {
                a0 += (double)SL(i, k)     * (double)SX(k, c);
                a1 += (double)SL(i, k + 1) * (double)SX(k + 1, c);
                a2 += (double)SL(i, k + 2) * (double)SX(k + 2, c);
                a3 += (double)SL(i, k + 3) * (double)SX(k + 3, c);
            }
            for (; k < i; k++) a0 += (double)SL(i, k) * (double)SX(k, c);
            SX(i, c) = (float)(-(double)rd[i] * ((a0 + a1) + (a2 + a3)));
        }
    }
    __syncthreads();

    for (int idx = tid; idx < 128 * 128; idx += 128) {
        int r = idx >> 7, c = idx & 127;
        out[(long long)r * ldout + c] = SX(r, c);
    }
#undef SL
#undef SX
}

// ---------------- init: W top-right zeros, spread = 1.0, nll acc = 0 ----------------
__global__ void init_kernel(float* __restrict__ W, float* __restrict__ spread, double* acc)
{
    int idx = blockIdx.x * blockDim.x + threadIdx.x;
    if (idx < 128 * 16384) {            // 128 batches x 128x128 TR block
        int b  = idx >> 14;
        int ij = idx & 16383;
        int r  = ij >> 7, c = ij & 127;
        W[(long long)b * 65536 + r * 256 + 128 + c] = 0.f;
    }
    if (idx < BB * NQ) spread[idx] = 1.f;
    if (idx == 0) *acc = 0.0;
}

// ---------------- sig fill (diagonal [B,Q,64,64]) ----------------
__global__ void sigfill_kernel(float* __restrict__ sig, const float* __restrict__ spread,
                               const float* __restrict__ sig_eps)
{
    long long i = (long long)blockIdx.x * blockDim.x + threadIdx.x;   // float4 index
    const long long NV = SIG_N / 4;
    if (i >= NV) return;
    long long pos = i * 4;
    int bq = (int)(pos >> 12);
    int k  = (int)(pos & 4095);
    int r  = k >> 6;
    int c  = k & 63;
    float sf = spread[bq] * sig_eps[0];
    float4 o;
    o.x = (c     == r) ? sf : 0.f;
    o.y = (c + 1 == r) ? sf : 0.f;
    o.z = (c + 2 == r) ? sf : 0.f;
    o.w = (c + 3 == r) ? sf : 0.f;
    *(float4*)(sig + pos) = o;
}

// ---------------- nll ----------------
__global__ void nll_kernel(const float* __restrict__ yq, const float* __restrict__ mu,
                           const float* __restrict__ spread, const float* __restrict__ sig_eps,
                           double* __restrict__ acc)
{
    int bq = blockIdx.x * blockDim.x + threadIdx.x;
    float se = sig_eps[0];
    float sp = spread[bq];
    const float* y = yq + (long long)bq * DOUT;
    const float* m = mu + (long long)bq * DOUT;
    float q = 0.f;
#pragma unroll
    for (int d = 0; d < DOUT; d++) { float r = y[d] - m[d]; q += r * r; }
    float val = (float)DOUT * (logf(sp) + logf(se)) + q / (sp * se);

    __shared__ double s[256];
    s[threadIdx.x] = (double)val;
    __syncthreads();
    for (int o = 128; o; o >>= 1) {
        if (threadIdx.x < o) s[threadIdx.x] += s[threadIdx.x + o];
        __syncthreads();
    }
    if (threadIdx.x == 0) atomicAdd(acc, s[0]);
}

__global__ void nll_final_kernel(const double* __restrict__ acc, float* __restrict__ out)
{
    out[0] = (float)(acc[0] / (double)(BB * NQ));
}

// ---------------- launch ----------------
extern "C" void kernel_launch(void* const* d_in, const int* in_sizes, int n_in,
                              void* d_out, int out_size)
{
    const float* phiS = (const float*)d_in[0];   // [128,128,256]
    const float* yS   = (const float*)d_in[1];   // [128,128,64]
    const float* phiQ = (const float*)d_in[2];   // [128,512,256]
    const float* yQ   = (const float*)d_in[3];   // [128,512,64]
    const float* mpr  = (const float*)d_in[4];   // [256,64]
    const float* asym = (const float*)d_in[5];   // [256,256]
    const float* se   = (const float*)d_in[6];   // [1]
    float* out = (float*)d_out;

    float*  buf  = nullptr;
    double* nacc = nullptr;
    cudaGetSymbolAddress((void**)&buf,  g_buf);
    cudaGetSymbolAddress((void**)&nacc, g_nll_acc);

    float* Sp   = buf + OFF_SP;
    float* Mpn  = buf + OFF_MPN;
    float* Sinv = buf + OFF_SINV;
    float* W    = buf + OFF_W;
    float* V    = buf + OFF_V;
    float* X    = buf + OFF_X;
    float* Sc   = buf + OFF_SC;
    float* Rhs  = buf + OFF_RHS;
    float* Tt   = buf + OFF_T;
    float* Mm   = buf + OFF_M;
    float* Spr  = buf + OFF_SPREAD;

    float* mu_out  = out;
    float* sig_out = out + MU_N;
    float* nll_out = out + MU_N + SIG_N;

    const int CHOL_SMEM = (2 * 128 * 129 + 128 + 4) * 4;
    cudaFuncSetAttribute(chol_linv_kernel, cudaFuncAttributeMaxDynamicSharedMemorySize, CHOL_SMEM);

    init_kernel<<<(128 * 16384 + 255) / 256, 256>>>(W, Spr, nacc);

    // Sp = asym @ asym^T
    gemm_k<128, 128, false><<<dim3(2, 2, 1), 256>>>(256, 256, 256,
        asym, 256, 0, 0,  asym, 256, 0, 1,  nullptr, 0, 0, 1.f,  Sp, 256, 0, nullptr);
    // Mpn = Sp @ m_prior
    gemm_k<128, 64, false><<<dim3(1, 2, 1), 256>>>(256, 64, 256,
        Sp, 256, 0, 0,  mpr, 64, 0, 0,  nullptr, 0, 0, 1.f,  Mpn, 64, 0, nullptr);
    // Sinv[b] = phiS^T phiS + Sp
    gemm_k<128, 128, false><<<dim3(2, 2, BB), 256>>>(256, 256, 128,
        phiS, 256, 32768, 1,  phiS, 256, 32768, 0,  Sp, 256, 0, 1.f,  Sinv, 256, 65536, nullptr);
    // Rhs[b] = phiS^T yS + Mpn
    gemm_k<128, 64, false><<<dim3(1, 2, BB), 256>>>(256, 64, 128,
        phiS, 256, 32768, 1,  yS, 64, 8192, 0,  Mpn, 64, 0, 1.f,  Rhs, 64, 16384, nullptr);

    // WA = LA^{-1} of A block -> W top-left
    chol_linv_kernel<<<BB, 128, CHOL_SMEM>>>(Sinv, 256, 65536, W, 256, 65536);
    // V = WA @ Bblk
    gemm_k<128, 128, false><<<dim3(1, 1, BB), 256>>>(128, 128, 128,
        W, 256, 65536, 0,  Sinv + 128, 256, 65536, 0,  nullptr, 0, 0, 1.f,  V, 128, 16384, nullptr);
    // X = WA^T @ V  (= A^{-1} B)
    gemm_k<128, 128, false><<<dim3(1, 1, BB), 256>>>(128, 128, 128,
        W, 256, 65536, 1,  V, 128, 16384, 0,  nullptr, 0, 0, 1.f,  X, 128, 16384, nullptr);
    // Sc = Dblk - Bblk^T X
    gemm_k<128, 128, false><<<dim3(1, 1, BB), 256>>>(128, 128, 128,
        Sinv + 128, 256, 65536, 1,  X, 128, 16384, 0,
        Sinv + 128 * 256 + 128, 256, 65536, -1.f,  Sc, 128, 16384, nullptr);
    // WS = LSc^{-1} -> W bottom-right
    chol_linv_kernel<<<BB, 128, CHOL_SMEM>>>(Sc, 128, 16384, W + 128 * 256 + 128, 256, 65536);
    // W_BL = -WS @ X^T
    gemm_k<128, 128, false><<<dim3(1, 1, BB), 256>>>(128, 128, 128,
        W + 128 * 256 + 128, 256, 65536, 0,  X, 128, 16384, 1,
        nullptr, 0, 0, -1.f,  W + 128 * 256, 256, 65536, nullptr);

    // t = W @ Rhs
    gemm_k<128, 64, false><<<dim3(1, 2, BB), 256>>>(256, 64, 256,
        W, 256, 65536, 0,  Rhs, 64, 16384, 0,  nullptr, 0, 0, 1.f,  Tt, 64, 16384, nullptr);
    // m = W^T @ t
    gemm_k<128, 64, false><<<dim3(1, 2, BB), 256>>>(256, 64, 256,
        W, 256, 65536, 1,  Tt, 64, 16384, 0,  nullptr, 0, 0, 1.f,  Mm, 64, 16384, nullptr);
    // mu = phiQ @ m   -> d_out
    gemm_k<128, 64, false><<<dim3(1, 4, BB), 256>>>(512, 64, 256,
        phiQ, 256, 131072, 0,  Mm, 64, 16384, 0,  nullptr, 0, 0, 1.f,  mu_out, 64, 32768, nullptr);
    // spread += rowsum((phiQ @ W^T)^2)  (fused, U never materialized)
    gemm_k<128, 128, true><<<dim3(2, 4, BB), 256>>>(512, 256, 256,
        phiQ, 256, 131072, 0,  W, 256, 65536, 1,  nullptr, 0, 0, 1.f,  nullptr, 0, 0, Spr);

    // sig (diagonal) fill
    sigfill_kernel<<<(unsigned int)(SIG_N / 4 / 256), 256>>>(sig_out, Spr, se);
    // nll
    nll_kernel<<<(BB * NQ) / 256, 256>>>(yQ, mu_out, Spr, se, nacc);
    nll_final_kernel<<<1, 1>>>(nacc, nll_out);

    (void)in_sizes; (void)n_in; (void)out_size;
}

// round 8
// speedup vs baseline: 3.3974x; 3.3974x over previous
#include <cuda_runtime.h>
#include <math.h>

#define BB   128
#define NS   128
#define NQ   512
#define DIN  256
#define DOUT 64

#define MU_N  ((long long)BB * NQ * DOUT)            // 4,194,304
#define SIG_N ((long long)BB * NQ * DOUT * DOUT)     // 134,217,728

// ---------------- scratch (floats) ----------------
#define OFF_SP     0LL
#define OFF_MPN    65536LL
#define OFF_SINV   81920LL
#define OFF_W      8470528LL
#define OFF_V      16859136LL
#define OFF_X      18956288LL
#define OFF_SC     21053440LL
#define OFF_RHS    23150592LL
#define OFF_T      25247744LL
#define OFF_M      27344896LL
#define OFF_SPREAD 29442048LL
#define BUF_TOTAL  29507584LL

__device__ float  g_buf[BUF_TOTAL];
__device__ double g_nll_acc;

// ======================================================================
// Batched SGEMM, 128x(BN) CTA tile, 256 threads, 8x(BN/16) reg tile,
// double-buffered shared memory (one __syncthreads per K-tile).
// C[b] = alpha * op(A[b]) @ op(B[b]) + (Dd ? Dd[b] : 0)
// TA==0: A is MxK row-major;  TA==1: A stored KxM (op(A)=A^T)
// TB==0: B is KxN row-major;  TB==1: B stored NxK (op(B)=B^T)
// SPREPI: store nothing; rowsum(elem^2) atomically added into spread[b*M+row].
// Requires M%BM==0, N%BN==0, K%16==0, 16B-aligned pointers.
// ======================================================================
template<int BM, int BN, int TA, int TB, bool SPREPI>
__global__ void __launch_bounds__(256, 2) gemm_k(
    int M, int N, int K,
    const float* __restrict__ A, int lda, long long sA,
    const float* __restrict__ B, int ldb, long long sB,
    const float* __restrict__ Dd, int ldd, long long sD,
    float alpha,
    float* __restrict__ C, int ldc, long long sC,
    float* __restrict__ spread)
{
    constexpr int TM  = BM / 16;           // 8
    constexpr int TN  = BN / 16;           // 8 or 4
    constexpr int LAS = BM + 4;
    constexpr int LBS = BN + 4;
    constexpr int NLA = (BM * 4) / 256;    // float4 loads/thread for A (2)
    constexpr int NLB = (BN * 4) / 256;    // 2 or 1

    __shared__ float As[2][16][LAS];
    __shared__ float Bs[2][16][LBS];

    const int b  = blockIdx.z;
    const float* Ab = A + (long long)b * sA;
    const float* Bb = B + (long long)b * sB;

    const int m0 = blockIdx.y * BM;
    const int n0 = blockIdx.x * BN;
    const int tid = threadIdx.x;
    const int tx = tid & 15;
    const int ty = tid >> 4;

    float4 ra[NLA], rb[NLB];

    auto ldA = [&](int k0) {
        if constexpr (TA == 0) {
#pragma unroll
            for (int q = 0; q < NLA; q++) {
                int p = tid + q * 256;
                int m = p >> 2, kq = (p & 3) * 4;
                ra[q] = *(const float4*)(Ab + (long long)(m0 + m) * lda + k0 + kq);
            }
        } else {
#pragma unroll
            for (int q = 0; q < NLA; q++) {
                int p = tid + q * 256;
                int k = p / (BM / 4), mq = (p % (BM / 4)) * 4;
                ra[q] = *(const float4*)(Ab + (long long)(k0 + k) * lda + m0 + mq);
            }
        }
    };
    auto stA = [&](int s) {
        if constexpr (TA == 0) {
#pragma unroll
            for (int q = 0; q < NLA; q++) {
                int p = tid + q * 256;
                int m = p >> 2, kq = (p & 3) * 4;
                As[s][kq + 0][m] = ra[q].x; As[s][kq + 1][m] = ra[q].y;
                As[s][kq + 2][m] = ra[q].z; As[s][kq + 3][m] = ra[q].w;
            }
        } else {
#pragma unroll
            for (int q = 0; q < NLA; q++) {
                int p = tid + q * 256;
                int k = p / (BM / 4), mq = (p % (BM / 4)) * 4;
                *(float4*)&As[s][k][mq] = ra[q];
            }
        }
    };
    auto ldB = [&](int k0) {
        if constexpr (TB == 0) {
#pragma unroll
            for (int q = 0; q < NLB; q++) {
                int p = tid + q * 256;
                int k = p / (BN / 4), nq = (p % (BN / 4)) * 4;
                rb[q] = *(const float4*)(Bb + (long long)(k0 + k) * ldb + n0 + nq);
            }
        } else {
#pragma unroll
            for (int q = 0; q < NLB; q++) {
                int p = tid + q * 256;
                int n = p >> 2, kq = (p & 3) * 4;
                rb[q] = *(const float4*)(Bb + (long long)(n0 + n) * ldb + k0 + kq);
            }
        }
    };
    auto stB = [&](int s) {
        if constexpr (TB == 0) {
#pragma unroll
            for (int q = 0; q < NLB; q++) {
                int p = tid + q * 256;
                int k = p / (BN / 4), nq = (p % (BN / 4)) * 4;
                *(float4*)&Bs[s][k][nq] = rb[q];
            }
        } else {
#pragma unroll
            for (int q = 0; q < NLB; q++) {
                int p = tid + q * 256;
                int n = p >> 2, kq = (p & 3) * 4;
                Bs[s][kq + 0][n] = rb[q].x; Bs[s][kq + 1][n] = rb[q].y;
                Bs[s][kq + 2][n] = rb[q].z; Bs[s][kq + 3][n] = rb[q].w;
            }
        }
    };

    float acc[TM][TN];
#pragma unroll
    for (int i = 0; i < TM; i++)
#pragma unroll
        for (int j = 0; j < TN; j++) acc[i][j] = 0.f;

    // prologue: stage tile 0
    ldA(0); ldB(0);
    stA(0); stB(0);
    __syncthreads();

    int cur = 0;
#pragma unroll 1
    for (int k0 = 0; k0 < K; k0 += 16) {
        const bool has_next = (k0 + 16 < K);
        if (has_next) { ldA(k0 + 16); ldB(k0 + 16); }

#pragma unroll
        for (int k = 0; k < 16; k++) {
            float a[TM], bv[TN];
#pragma unroll
            for (int g = 0; g < TM / 4; g++)
                *(float4*)&a[g * 4] = *(const float4*)&As[cur][k][g * 64 + ty * 4];
#pragma unroll
            for (int g = 0; g < TN / 4; g++)
                *(float4*)&bv[g * 4] = *(const float4*)&Bs[cur][k][g * 64 + tx * 4];
#pragma unroll
            for (int i = 0; i < TM; i++)
#pragma unroll
                for (int j = 0; j < TN; j++)
                    acc[i][j] += a[i] * bv[j];
        }

        if (has_next) {
            stA(cur ^ 1); stB(cur ^ 1);
            __syncthreads();
        }
        cur ^= 1;
    }

    if (!SPREPI) {
        float* Cb = C + (long long)b * sC;
#pragma unroll
        for (int i = 0; i < TM; i++) {
            int m = m0 + (i / 4) * 64 + ty * 4 + (i & 3);
#pragma unroll
            for (int gj = 0; gj < TN / 4; gj++) {
                int n = n0 + gj * 64 + tx * 4;
                float4 o;
                o.x = alpha * acc[i][gj * 4 + 0];
                o.y = alpha * acc[i][gj * 4 + 1];
                o.z = alpha * acc[i][gj * 4 + 2];
                o.w = alpha * acc[i][gj * 4 + 3];
                if (Dd) {
                    float4 d = *(const float4*)(Dd + (long long)b * sD + (long long)m * ldd + n);
                    o.x += d.x; o.y += d.y; o.z += d.z; o.w += d.w;
                }
                *(float4*)(Cb + (long long)m * ldc + n) = o;
            }
        }
    } else {
#pragma unroll
        for (int i = 0; i < TM; i++) {
            float s = 0.f;
#pragma unroll
            for (int j = 0; j < TN; j++) s += acc[i][j] * acc[i][j];
            s += __shfl_xor_sync(0xFFFFFFFFu, s, 1);
            s += __shfl_xor_sync(0xFFFFFFFFu, s, 2);
            s += __shfl_xor_sync(0xFFFFFFFFu, s, 4);
            s += __shfl_xor_sync(0xFFFFFFFFu, s, 8);
            if (tx == 0) {
                int m = m0 + (i / 4) * 64 + ty * 4 + (i & 3);
                atomicAdd(&spread[(long long)b * M + m], s);
            }
        }
    }
}

// ======================================================================
// Per-CTA smem Cholesky + triangular inverse (n=128).
// fp32 with 4-way-split Kahan compensated accumulation (FP64 is slow on
// sm_103a; Kahan gives near-double summation accuracy on the FMA/ALU pipes).
// Output: Linv (lower), A^{-1} = Linv^T Linv.
// ======================================================================
#define KADD(s, c, x) { float _y = (x) - (c); float _t = (s) + _y; (c) = (_t - (s)) - _y; (s) = _t; }

__global__ void chol_linv_kernel(const float* __restrict__ in, int ldin, long long strideIn,
                                 float* __restrict__ Lout, int ldout, long long strideOut)
{
    extern __shared__ float sh[];
    float* sL  = sh;                 // [128][129]
    float* sX  = sh + 128 * 129;     // [128][129]
    float* rd  = sh + 2 * 128 * 129; // [128]
    float* sdi = rd + 128;           // [1]
#define SL(i,k) sL[(i) * 129 + (k)]
#define SX(i,k) sX[(i) * 129 + (k)]

    int b   = blockIdx.x;
    int tid = threadIdx.x;          // 0..127
    const float* A = in + (long long)b * strideIn;
    float* out = Lout + (long long)b * strideOut;

    for (int idx = tid; idx < 128 * 128; idx += 128) {
        int r = idx >> 7, c = idx & 127;
        SL(r, c) = A[(long long)r * ldin + c];
    }
    __syncthreads();

    // left-looking Cholesky (lower), Kahan accumulation
    for (int j = 0; j < 128; j++) {
        float t = 0.f;
        if (tid >= j) {
            float s0 = 0.f, c0 = 0.f, s1 = 0.f, c1 = 0.f;
            float s2 = 0.f, c2 = 0.f, s3 = 0.f, c3 = 0.f;
            int k = 0;
            for (; k + 3 < j; k += 4) {
                KADD(s0, c0, SL(tid, k)     * SL(j, k));
                KADD(s1, c1, SL(tid, k + 1) * SL(j, k + 1));
                KADD(s2, c2, SL(tid, k + 2) * SL(j, k + 2));
                KADD(s3, c3, SL(tid, k + 3) * SL(j, k + 3));
            }
            for (; k < j; k++) KADD(s0, c0, SL(tid, k) * SL(j, k));
            float sum = ((s0 + s1) + (s2 + s3)) + ((c0 + c1) + (c2 + c3));
            t = SL(tid, j) - sum;
        }
        if (tid == j) {
            float d = sqrtf(t);
            SL(j, j) = d;
            sdi[0] = 1.f / d;
        }
        __syncthreads();
        if (tid > j) SL(tid, j) = t * sdi[0];
        __syncthreads();
    }

    rd[tid] = 1.f / SL(tid, tid);
    __syncthreads();

    // column-parallel triangular inverse: sX = L^{-1}, Kahan accumulation
    {
        int c = tid;
        for (int i = 0; i < c; i++) SX(i, c) = 0.f;
        SX(c, c) = rd[c];
        for (int i = c + 1; i < 128; i++) {
            float s0 = 0.f, c0 = 0.f, s1 = 0.f, c1 = 0.f;
            float s2 = 0.f, c2 = 0.f, s3 = 0.f, c3 = 0.f;
            int k = c;
            for (; k + 3 < i; k += 4) {
                KADD(s0, c0, SL(i, k)     * SX(k, c));
                KADD(s1, c1, SL(i, k + 1) * SX(k + 1, c));
                KADD(s2, c2, SL(i, k + 2) * SX(k + 2, c));
                KADD(s3, c3, SL(i, k + 3) * SX(k + 3, c));
            }
            for (; k < i; k++) KADD(s0, c0, SL(i, k) * SX(k, c));
            float sum = ((s0 + s1) + (s2 + s3)) + ((c0 + c1) + (c2 + c3));
            SX(i, c) = -rd[i] * sum;
        }
    }
    __syncthreads();

    for (int idx = tid; idx < 128 * 128; idx += 128) {
        int r = idx >> 7, c = idx & 127;
        out[(long long)r * ldout + c] = SX(r, c);
    }
#undef SL
#undef SX
}

// ---------------- init: W top-right zeros, spread = 1.0, nll acc = 0 ----------------
__global__ void init_kernel(float* __restrict__ W, float* __restrict__ spread, double* acc)
{
    int idx = blockIdx.x * blockDim.x + threadIdx.x;
    if (idx < 128 * 16384) {
        int b  = idx >> 14;
        int ij = idx & 16383;
        int r  = ij >> 7, c = ij & 127;
        W[(long long)b * 65536 + r * 256 + 128 + c] = 0.f;
    }
    if (idx < BB * NQ) spread[idx] = 1.f;
    if (idx == 0) *acc = 0.0;
}

// ---------------- sig fill (diagonal [B,Q,64,64]) ----------------
__global__ void sigfill_kernel(float* __restrict__ sig, const float* __restrict__ spread,
                               const float* __restrict__ sig_eps)
{
    long long i = (long long)blockIdx.x * blockDim.x + threadIdx.x;   // float4 index
    const long long NV = SIG_N / 4;
    if (i >= NV) return;
    long long pos = i * 4;
    int bq = (int)(pos >> 12);
    int k  = (int)(pos & 4095);
    int r  = k >> 6;
    int c  = k & 63;
    float sf = spread[bq] * sig_eps[0];
    float4 o;
    o.x = (c     == r) ? sf : 0.f;
    o.y = (c + 1 == r) ? sf : 0.f;
    o.z = (c + 2 == r) ? sf : 0.f;
    o.w = (c + 3 == r) ? sf : 0.f;
    *(float4*)(sig + pos) = o;
}

// ---------------- nll ----------------
__global__ void nll_kernel(const float* __restrict__ yq, const float* __restrict__ mu,
                           const float* __restrict__ spread, const float* __restrict__ sig_eps,
                           double* __restrict__ acc)
{
    int bq = blockIdx.x * blockDim.x + threadIdx.x;
    float se = sig_eps[0];
    float sp = spread[bq];
    const float* y = yq + (long long)bq * DOUT;
    const float* m = mu + (long long)bq * DOUT;
    float q = 0.f;
#pragma unroll
    for (int d = 0; d < DOUT; d++) { float r = y[d] - m[d]; q += r * r; }
    float val = (float)DOUT * (logf(sp) + logf(se)) + q / (sp * se);

    __shared__ double s[256];
    s[threadIdx.x] = (double)val;
    __syncthreads();
    for (int o = 128; o; o >>= 1) {
        if (threadIdx.x < o) s[threadIdx.x] += s[threadIdx.x + o];
        __syncthreads();
    }
    if (threadIdx.x == 0) atomicAdd(acc, s[0]);
}

__global__ void nll_final_kernel(const double* __restrict__ acc, float* __restrict__ out)
{
    out[0] = (float)(acc[0] / (double)(BB * NQ));
}

// ---------------- launch ----------------
extern "C" void kernel_launch(void* const* d_in, const int* in_sizes, int n_in,
                              void* d_out, int out_size)
{
    const float* phiS = (const float*)d_in[0];   // [128,128,256]
    const float* yS   = (const float*)d_in[1];   // [128,128,64]
    const float* phiQ = (const float*)d_in[2];   // [128,512,256]
    const float* yQ   = (const float*)d_in[3];   // [128,512,64]
    const float* mpr  = (const float*)d_in[4];   // [256,64]
    const float* asym = (const float*)d_in[5];   // [256,256]
    const float* se   = (const float*)d_in[6];   // [1]
    float* out = (float*)d_out;

    float*  buf  = nullptr;
    double* nacc = nullptr;
    cudaGetSymbolAddress((void**)&buf,  g_buf);
    cudaGetSymbolAddress((void**)&nacc, g_nll_acc);

    float* Sp   = buf + OFF_SP;
    float* Mpn  = buf + OFF_MPN;
    float* Sinv = buf + OFF_SINV;
    float* W    = buf + OFF_W;
    float* V    = buf + OFF_V;
    float* X    = buf + OFF_X;
    float* Sc   = buf + OFF_SC;
    float* Rhs  = buf + OFF_RHS;
    float* Tt   = buf + OFF_T;
    float* Mm   = buf + OFF_M;
    float* Spr  = buf + OFF_SPREAD;

    float* mu_out  = out;
    float* sig_out = out + MU_N;
    float* nll_out = out + MU_N + SIG_N;

    const int CHOL_SMEM = (2 * 128 * 129 + 128 + 4) * 4;
    cudaFuncSetAttribute(chol_linv_kernel, cudaFuncAttributeMaxDynamicSharedMemorySize, CHOL_SMEM);

    init_kernel<<<(128 * 16384 + 255) / 256, 256>>>(W, Spr, nacc);

    // Sp = asym @ asym^T
    gemm_k<128, 128, 0, 1, false><<<dim3(2, 2, 1), 256>>>(256, 256, 256,
        asym, 256, 0,  asym, 256, 0,  nullptr, 0, 0, 1.f,  Sp, 256, 0, nullptr);
    // Mpn = Sp @ m_prior
    gemm_k<128, 64, 0, 0, false><<<dim3(1, 2, 1), 256>>>(256, 64, 256,
        Sp, 256, 0,  mpr, 64, 0,  nullptr, 0, 0, 1.f,  Mpn, 64, 0, nullptr);
    // Sinv[b] = phiS^T phiS + Sp
    gemm_k<128, 128, 1, 0, false><<<dim3(2, 2, BB), 256>>>(256, 256, 128,
        phiS, 256, 32768,  phiS, 256, 32768,  Sp, 256, 0, 1.f,  Sinv, 256, 65536, nullptr);
    // Rhs[b] = phiS^T yS + Mpn
    gemm_k<128, 64, 1, 0, false><<<dim3(1, 2, BB), 256>>>(256, 64, 128,
        phiS, 256, 32768,  yS, 64, 8192,  Mpn, 64, 0, 1.f,  Rhs, 64, 16384, nullptr);

    // WA = LA^{-1} of A block -> W top-left
    chol_linv_kernel<<<BB, 128, CHOL_SMEM>>>(Sinv, 256, 65536, W, 256, 65536);
    // V = WA @ Bblk
    gemm_k<128, 128, 0, 0, false><<<dim3(1, 1, BB), 256>>>(128, 128, 128,
        W, 256, 65536,  Sinv + 128, 256, 65536,  nullptr, 0, 0, 1.f,  V, 128, 16384, nullptr);
    // X = WA^T @ V  (= A^{-1} B)
    gemm_k<128, 128, 1, 0, false><<<dim3(1, 1, BB), 256>>>(128, 128, 128,
        W, 256, 65536,  V, 128, 16384,  nullptr, 0, 0, 1.f,  X, 128, 16384, nullptr);
    // Sc = Dblk - Bblk^T X
    gemm_k<128, 128, 1, 0, false><<<dim3(1, 1, BB), 256>>>(128, 128, 128,
        Sinv + 128, 256, 65536,  X, 128, 16384,
        Sinv + 128 * 256 + 128, 256, 65536, -1.f,  Sc, 128, 16384, nullptr);
    // WS = LSc^{-1} -> W bottom-right
    chol_linv_kernel<<<BB, 128, CHOL_SMEM>>>(Sc, 128, 16384, W + 128 * 256 + 128, 256, 65536);
    // W_BL = -WS @ X^T
    gemm_k<128, 128, 0, 1, false><<<dim3(1, 1, BB), 256>>>(128, 128, 128,
        W + 128 * 256 + 128, 256, 65536,  X, 128, 16384,
        nullptr, 0, 0, -1.f,  W + 128 * 256, 256, 65536, nullptr);

    // t = W @ Rhs
    gemm_k<128, 64, 0, 0, false><<<dim3(1, 2, BB), 256>>>(256, 64, 256,
        W, 256, 65536,  Rhs, 64, 16384,  nullptr, 0, 0, 1.f,  Tt, 64, 16384, nullptr);
    // m = W^T @ t
    gemm_k<128, 64, 1, 0, false><<<dim3(1, 2, BB), 256>>>(256, 64, 256,
        W, 256, 65536,  Tt, 64, 16384,  nullptr, 0, 0, 1.f,  Mm, 64, 16384, nullptr);
    // mu = phiQ @ m   -> d_out
    gemm_k<128, 64, 0, 0, false><<<dim3(1, 4, BB), 256>>>(512, 64, 256,
        phiQ, 256, 131072,  Mm, 64, 16384,  nullptr, 0, 0, 1.f,  mu_out, 64, 32768, nullptr);
    // spread += rowsum((phiQ @ W^T)^2)  (fused, U never materialized)
    gemm_k<128, 128, 0, 1, true><<<dim3(2, 4, BB), 256>>>(512, 256, 256,
        phiQ, 256, 131072,  W, 256, 65536,  nullptr, 0, 0, 1.f,  nullptr, 0, 0, Spr);

    // sig (diagonal) fill
    sigfill_kernel<<<(unsigned int)(SIG_N / 4 / 256), 256>>>(sig_out, Spr, se);
    // nll
    nll_kernel<<<(BB * NQ) / 256, 256>>>(yQ, mu_out, Spr, se, nacc);
    nll_final_kernel<<<1, 1>>>(nacc, nll_out);

    (void)in_sizes; (void)n_in; (void)out_size;
}

// round 10
// speedup vs baseline: 3.6383x; 1.0709x over previous
#include <cuda_runtime.h>
#include <math.h>

#define BB   128
#define NS   128
#define NQ   512
#define DIN  256
#define DOUT 64

#define MU_N  ((long long)BB * NQ * DOUT)            // 4,194,304
#define SIG_N ((long long)BB * NQ * DOUT * DOUT)     // 134,217,728

// ---------------- scratch (floats) ----------------
#define OFF_SP     0LL
#define OFF_MPN    65536LL
#define OFF_SINV   81920LL
#define OFF_W      8470528LL
#define OFF_V      16859136LL
#define OFF_X      18956288LL
#define OFF_SC     21053440LL
#define OFF_RHS    23150592LL
#define OFF_T      25247744LL
#define OFF_M      27344896LL
#define OFF_SPREAD 29442048LL
#define BUF_TOTAL  29507584LL

__device__ float  g_buf[BUF_TOTAL];
__device__ double g_nll_acc;

// ======================================================================
// Batched SGEMM, 128x(BN) CTA tile, 256 threads, 8x(BN/16) reg tile,
// double-buffered shared memory (one __syncthreads per K-tile).
// C[b] = alpha * op(A[b]) @ op(B[b]) + (Dd ? Dd[b] : 0)
// TA==0: A is MxK row-major;  TA==1: A stored KxM (op(A)=A^T)
// TB==0: B is KxN row-major;  TB==1: B stored NxK (op(B)=B^T)
// SPREPI: store nothing; rowsum(elem^2) atomically added into spread[b*M+row].
// ======================================================================
template<int BM, int BN, int TA, int TB, bool SPREPI>
__global__ void __launch_bounds__(256, 2) gemm_k(
    int M, int N, int K,
    const float* __restrict__ A, int lda, long long sA,
    const float* __restrict__ B, int ldb, long long sB,
    const float* __restrict__ Dd, int ldd, long long sD,
    float alpha,
    float* __restrict__ C, int ldc, long long sC,
    float* __restrict__ spread)
{
    constexpr int TM  = BM / 16;           // 8
    constexpr int TN  = BN / 16;           // 8 or 4
    constexpr int LAS = BM + 4;
    constexpr int LBS = BN + 4;
    constexpr int NLA = (BM * 4) / 256;    // float4 loads/thread for A (2)
    constexpr int NLB = (BN * 4) / 256;    // 2 or 1

    __shared__ float As[2][16][LAS];
    __shared__ float Bs[2][16][LBS];

    const int b  = blockIdx.z;
    const float* Ab = A + (long long)b * sA;
    const float* Bb = B + (long long)b * sB;

    const int m0 = blockIdx.y * BM;
    const int n0 = blockIdx.x * BN;
    const int tid = threadIdx.x;
    const int tx = tid & 15;
    const int ty = tid >> 4;

    float4 ra[NLA], rb[NLB];

    auto ldA = [&](int k0) {
        if constexpr (TA == 0) {
#pragma unroll
            for (int q = 0; q < NLA; q++) {
                int p = tid + q * 256;
                int m = p >> 2, kq = (p & 3) * 4;
                ra[q] = *(const float4*)(Ab + (long long)(m0 + m) * lda + k0 + kq);
            }
        } else {
#pragma unroll
            for (int q = 0; q < NLA; q++) {
                int p = tid + q * 256;
                int k = p / (BM / 4), mq = (p % (BM / 4)) * 4;
                ra[q] = *(const float4*)(Ab + (long long)(k0 + k) * lda + m0 + mq);
            }
        }
    };
    auto stA = [&](int s) {
        if constexpr (TA == 0) {
#pragma unroll
            for (int q = 0; q < NLA; q++) {
                int p = tid + q * 256;
                int m = p >> 2, kq = (p & 3) * 4;
                As[s][kq + 0][m] = ra[q].x; As[s][kq + 1][m] = ra[q].y;
                As[s][kq + 2][m] = ra[q].z; As[s][kq + 3][m] = ra[q].w;
            }
        } else {
#pragma unroll
            for (int q = 0; q < NLA; q++) {
                int p = tid + q * 256;
                int k = p / (BM / 4), mq = (p % (BM / 4)) * 4;
                *(float4*)&As[s][k][mq] = ra[q];
            }
        }
    };
    auto ldB = [&](int k0) {
        if constexpr (TB == 0) {
#pragma unroll
            for (int q = 0; q < NLB; q++) {
                int p = tid + q * 256;
                int k = p / (BN / 4), nq = (p % (BN / 4)) * 4;
                rb[q] = *(const float4*)(Bb + (long long)(k0 + k) * ldb + n0 + nq);
            }
        } else {
#pragma unroll
            for (int q = 0; q < NLB; q++) {
                int p = tid + q * 256;
                int n = p >> 2, kq = (p & 3) * 4;
                rb[q] = *(const float4*)(Bb + (long long)(n0 + n) * ldb + k0 + kq);
            }
        }
    };
    auto stB = [&](int s) {
        if constexpr (TB == 0) {
#pragma unroll
            for (int q = 0; q < NLB; q++) {
                int p = tid + q * 256;
                int k = p / (BN / 4), nq = (p % (BN / 4)) * 4;
                *(float4*)&Bs[s][k][nq] = rb[q];
            }
        } else {
#pragma unroll
            for (int q = 0; q < NLB; q++) {
                int p = tid + q * 256;
                int n = p >> 2, kq = (p & 3) * 4;
                Bs[s][kq + 0][n] = rb[q].x; Bs[s][kq + 1][n] = rb[q].y;
                Bs[s][kq + 2][n] = rb[q].z; Bs[s][kq + 3][n] = rb[q].w;
            }
        }
    };

    float acc[TM][TN];
#pragma unroll
    for (int i = 0; i < TM; i++)
#pragma unroll
        for (int j = 0; j < TN; j++) acc[i][j] = 0.f;

    ldA(0); ldB(0);
    stA(0); stB(0);
    __syncthreads();

    int cur = 0;
#pragma unroll 1
    for (int k0 = 0; k0 < K; k0 += 16) {
        const bool has_next = (k0 + 16 < K);
        if (has_next) { ldA(k0 + 16); ldB(k0 + 16); }

#pragma unroll
        for (int k = 0; k < 16; k++) {
            float a[TM], bv[TN];
#pragma unroll
            for (int g = 0; g < TM / 4; g++)
                *(float4*)&a[g * 4] = *(const float4*)&As[cur][k][g * 64 + ty * 4];
#pragma unroll
            for (int g = 0; g < TN / 4; g++)
                *(float4*)&bv[g * 4] = *(const float4*)&Bs[cur][k][g * 64 + tx * 4];
#pragma unroll
            for (int i = 0; i < TM; i++)
#pragma unroll
                for (int j = 0; j < TN; j++)
                    acc[i][j] += a[i] * bv[j];
        }

        if (has_next) {
            stA(cur ^ 1); stB(cur ^ 1);
            __syncthreads();
        }
        cur ^= 1;
    }

    if (!SPREPI) {
        float* Cb = C + (long long)b * sC;
#pragma unroll
        for (int i = 0; i < TM; i++) {
            int m = m0 + (i / 4) * 64 + ty * 4 + (i & 3);
#pragma unroll
            for (int gj = 0; gj < TN / 4; gj++) {
                int n = n0 + gj * 64 + tx * 4;
                float4 o;
                o.x = alpha * acc[i][gj * 4 + 0];
                o.y = alpha * acc[i][gj * 4 + 1];
                o.z = alpha * acc[i][gj * 4 + 2];
                o.w = alpha * acc[i][gj * 4 + 3];
                if (Dd) {
                    float4 d = *(const float4*)(Dd + (long long)b * sD + (long long)m * ldd + n);
                    o.x += d.x; o.y += d.y; o.z += d.z; o.w += d.w;
                }
                *(float4*)(Cb + (long long)m * ldc + n) = o;
            }
        }
    } else {
#pragma unroll
        for (int i = 0; i < TM; i++) {
            float s = 0.f;
#pragma unroll
            for (int j = 0; j < TN; j++) s += acc[i][j] * acc[i][j];
            s += __shfl_xor_sync(0xFFFFFFFFu, s, 1);
            s += __shfl_xor_sync(0xFFFFFFFFu, s, 2);
            s += __shfl_xor_sync(0xFFFFFFFFu, s, 4);
            s += __shfl_xor_sync(0xFFFFFFFFu, s, 8);
            if (tx == 0) {
                int m = m0 + (i / 4) * 64 + ty * 4 + (i & 3);
                atomicAdd(&spread[(long long)b * M + m], s);
            }
        }
    }
}

// ======================================================================
// Per-CTA smem Cholesky + triangular inverse (n=128), Kahan-compensated fp32.
// Output: Linv (lower), A^{-1} = Linv^T Linv.
// ======================================================================
#define KADD(s, c, x) { float _y = (x) - (c); float _t = (s) + _y; (c) = (_t - (s)) - _y; (s) = _t; }

__global__ void chol_linv_kernel(const float* __restrict__ in, int ldin, long long strideIn,
                                 float* __restrict__ Lout, int ldout, long long strideOut)
{
    extern __shared__ float sh[];
    float* sL  = sh;                 // [128][129]
    float* sX  = sh + 128 * 129;     // [128][129]
    float* rd  = sh + 2 * 128 * 129; // [128]
    float* sdi = rd + 128;           // [1]
#define SL(i,k) sL[(i) * 129 + (k)]
#define SX(i,k) sX[(i) * 129 + (k)]

    int b   = blockIdx.x;
    int tid = threadIdx.x;          // 0..127
    const float* A = in + (long long)b * strideIn;
    float* out = Lout + (long long)b * strideOut;

    for (int idx = tid; idx < 128 * 128; idx += 128) {
        int r = idx >> 7, c = idx & 127;
        SL(r, c) = A[(long long)r * ldin + c];
    }
    __syncthreads();

    for (int j = 0; j < 128; j++) {
        float t = 0.f;
        if (tid >= j) {
            float s0 = 0.f, c0 = 0.f, s1 = 0.f, c1 = 0.f;
            float s2 = 0.f, c2 = 0.f, s3 = 0.f, c3 = 0.f;
            int k = 0;
            for (; k + 3 < j; k += 4) {
                KADD(s0, c0, SL(tid, k)     * SL(j, k));
                KADD(s1, c1, SL(tid, k + 1) * SL(j, k + 1));
                KADD(s2, c2, SL(tid, k + 2) * SL(j, k + 2));
                KADD(s3, c3, SL(tid, k + 3) * SL(j, k + 3));
            }
            for (; k < j; k++) KADD(s0, c0, SL(tid, k) * SL(j, k));
            float sum = ((s0 + s1) + (s2 + s3)) + ((c0 + c1) + (c2 + c3));
            t = SL(tid, j) - sum;
        }
        if (tid == j) {
            float d = sqrtf(t);
            SL(j, j) = d;
            sdi[0] = 1.f / d;
        }
        __syncthreads();
        if (tid > j) SL(tid, j) = t * sdi[0];
        __syncthreads();
    }

    rd[tid] = 1.f / SL(tid, tid);
    __syncthreads();

    {
        int c = tid;
        for (int i = 0; i < c; i++) SX(i, c) = 0.f;
        SX(c, c) = rd[c];
        for (int i = c + 1; i < 128; i++) {
            float s0 = 0.f, c0 = 0.f, s1 = 0.f, c1 = 0.f;
            float s2 = 0.f, c2 = 0.f, s3 = 0.f, c3 = 0.f;
            int k = c;
            for (; k + 3 < i; k += 4) {
                KADD(s0, c0, SL(i, k)     * SX(k, c));
                KADD(s1, c1, SL(i, k + 1) * SX(k + 1, c));
                KADD(s2, c2, SL(i, k + 2) * SX(k + 2, c));
                KADD(s3, c3, SL(i, k + 3) * SX(k + 3, c));
            }
            for (; k < i; k++) KADD(s0, c0, SL(i, k) * SX(k, c));
            float sum = ((s0 + s1) + (s2 + s3)) + ((c0 + c1) + (c2 + c3));
            SX(i, c) = -rd[i] * sum;
        }
    }
    __syncthreads();

    for (int idx = tid; idx < 128 * 128; idx += 128) {
        int r = idx >> 7, c = idx & 127;
        out[(long long)r * ldout + c] = SX(r, c);
    }
#undef SL
#undef SX
}

// ---------------- init: W top-right zeros, spread = 1.0, nll acc = 0 ----------------
__global__ void init_kernel(float* __restrict__ W, float* __restrict__ spread, double* acc)
{
    int idx = blockIdx.x * blockDim.x + threadIdx.x;
    if (idx < 128 * 16384) {
        int b  = idx >> 14;
        int ij = idx & 16383;
        int r  = ij >> 7, c = ij & 127;
        W[(long long)b * 65536 + r * 256 + 128 + c] = 0.f;
    }
    if (idx < BB * NQ) spread[idx] = 1.f;
    if (idx == 0) *acc = 0.0;
}

// ---------------- sig zero-fill (depends on nothing; runs on side stream) -------
__global__ void zerosig_kernel(float4* __restrict__ sig)
{
    long long i = (long long)blockIdx.x * blockDim.x + threadIdx.x;
    const long long NV = SIG_N / 4;
    const long long stride = (long long)gridDim.x * blockDim.x;
    float4 z = make_float4(0.f, 0.f, 0.f, 0.f);
    for (; i < NV; i += stride) sig[i] = z;
}

// ---------------- sig diagonal writer (8.4 MB scattered) ----------------
__global__ void sigdiag_kernel(float* __restrict__ sig, const float* __restrict__ spread,
                               const float* __restrict__ sig_eps)
{
    int idx = blockIdx.x * blockDim.x + threadIdx.x;   // bq*64 + r
    if (idx >= BB * NQ * DOUT) return;
    int bq = idx >> 6;
    int r  = idx & 63;
    sig[(long long)bq * 4096 + r * 65] = spread[bq] * sig_eps[0];
}

// ---------------- nll ----------------
__global__ void nll_kernel(const float* __restrict__ yq, const float* __restrict__ mu,
                           const float* __restrict__ spread, const float* __restrict__ sig_eps,
                           double* __restrict__ acc)
{
    int bq = blockIdx.x * blockDim.x + threadIdx.x;
    float se = sig_eps[0];
    float sp = spread[bq];
    const float* y = yq + (long long)bq * DOUT;
    const float* m = mu + (long long)bq * DOUT;
    float q = 0.f;
#pragma unroll
    for (int d = 0; d < DOUT; d++) { float r = y[d] - m[d]; q += r * r; }
    float val = (float)DOUT * (logf(sp) + logf(se)) + q / (sp * se);

    __shared__ double s[256];
    s[threadIdx.x] = (double)val;
    __syncthreads();
    for (int o = 128; o; o >>= 1) {
        if (threadIdx.x < o) s[threadIdx.x] += s[threadIdx.x + o];
        __syncthreads();
    }
    if (threadIdx.x == 0) atomicAdd(acc, s[0]);
}

__global__ void nll_final_kernel(const double* __restrict__ acc, float* __restrict__ out)
{
    out[0] = (float)(acc[0] / (double)(BB * NQ));
}

// ---------------- launch ----------------
extern "C" void kernel_launch(void* const* d_in, const int* in_sizes, int n_in,
                              void* d_out, int out_size)
{
    const float* phiS = (const float*)d_in[0];   // [128,128,256]
    const float* yS   = (const float*)d_in[1];   // [128,128,64]
    const float* phiQ = (const float*)d_in[2];   // [128,512,256]
    const float* yQ   = (const float*)d_in[3];   // [128,512,64]
    const float* mpr  = (const float*)d_in[4];   // [256,64]
    const float* asym = (const float*)d_in[5];   // [256,256]
    const float* se   = (const float*)d_in[6];   // [1]
    float* out = (float*)d_out;

    float*  buf  = nullptr;
    double* nacc = nullptr;
    cudaGetSymbolAddress((void**)&buf,  g_buf);
    cudaGetSymbolAddress((void**)&nacc, g_nll_acc);

    float* Sp   = buf + OFF_SP;
    float* Mpn  = buf + OFF_MPN;
    float* Sinv = buf + OFF_SINV;
    float* W    = buf + OFF_W;
    float* V    = buf + OFF_V;
    float* X    = buf + OFF_X;
    float* Sc   = buf + OFF_SC;
    float* Rhs  = buf + OFF_RHS;
    float* Tt   = buf + OFF_T;
    float* Mm   = buf + OFF_M;
    float* Spr  = buf + OFF_SPREAD;

    float* mu_out  = out;
    float* sig_out = out + MU_N;
    float* nll_out = out + MU_N + SIG_N;

    // Lazy-init side streams + events (first call is the uncaptured correctness
    // run; captured calls reuse them, producing fork/join edges in the graph).
    static cudaStream_t s2 = nullptr, s3 = nullptr;
    static cudaEvent_t evRoot, evInit, evZero, evMpn, evRhs, evV, evX, evW, evSpr;
    if (!s2) {
        cudaStreamCreateWithFlags(&s2, cudaStreamNonBlocking);
        cudaStreamCreateWithFlags(&s3, cudaStreamNonBlocking);
        cudaEventCreateWithFlags(&evRoot, cudaEventDisableTiming);
        cudaEventCreateWithFlags(&evInit, cudaEventDisableTiming);
        cudaEventCreateWithFlags(&evZero, cudaEventDisableTiming);
        cudaEventCreateWithFlags(&evMpn,  cudaEventDisableTiming);
        cudaEventCreateWithFlags(&evRhs,  cudaEventDisableTiming);
        cudaEventCreateWithFlags(&evV,    cudaEventDisableTiming);
        cudaEventCreateWithFlags(&evX,    cudaEventDisableTiming);
        cudaEventCreateWithFlags(&evW,    cudaEventDisableTiming);
        cudaEventCreateWithFlags(&evSpr,  cudaEventDisableTiming);
        const int CHOL_SMEM0 = (2 * 128 * 129 + 128 + 4) * 4;
        cudaFuncSetAttribute(chol_linv_kernel, cudaFuncAttributeMaxDynamicSharedMemorySize, CHOL_SMEM0);
    }
    const int CHOL_SMEM = (2 * 128 * 129 + 128 + 4) * 4;

    // ---- fork side streams off the main (capture) stream ----
    cudaEventRecord(evRoot, 0);
    cudaStreamWaitEvent(s2, evRoot, 0);
    cudaStreamWaitEvent(s3, evRoot, 0);

    // s2: init (W_TR zeros, spread=1, acc=0) then the big sig zero-fill —
    // overlaps the FFMA-bound compute chain (DRAM is ~96% idle there).
    init_kernel<<<(128 * 16384 + 255) / 256, 256, 0, s2>>>(W, Spr, nacc);
    cudaEventRecord(evInit, s2);
    zerosig_kernel<<<8192, 256, 0, s2>>>((float4*)sig_out);
    cudaEventRecord(evZero, s2);

    // main: prior precision chain
    gemm_k<128, 128, 0, 1, false><<<dim3(2, 2, 1), 256>>>(256, 256, 256,
        asym, 256, 0,  asym, 256, 0,  nullptr, 0, 0, 1.f,  Sp, 256, 0, nullptr);
    gemm_k<128, 64, 0, 0, false><<<dim3(1, 2, 1), 256>>>(256, 64, 256,
        Sp, 256, 0,  mpr, 64, 0,  nullptr, 0, 0, 1.f,  Mpn, 64, 0, nullptr);
    cudaEventRecord(evMpn, 0);

    // s3: Rhs[b] = phiS^T yS + Mpn   (concurrent with Sinv + chol1)
    cudaStreamWaitEvent(s3, evMpn, 0);
    gemm_k<128, 64, 1, 0, false><<<dim3(1, 2, BB), 256, 0, s3>>>(256, 64, 128,
        phiS, 256, 32768,  yS, 64, 8192,  Mpn, 64, 0, 1.f,  Rhs, 64, 16384, nullptr);
    cudaEventRecord(evRhs, s3);

    // main: Sinv[b] = phiS^T phiS + Sp
    gemm_k<128, 128, 1, 0, false><<<dim3(2, 2, BB), 256>>>(256, 256, 128,
        phiS, 256, 32768,  phiS, 256, 32768,  Sp, 256, 0, 1.f,  Sinv, 256, 65536, nullptr);
    // WA = LA^{-1} -> W top-left
    chol_linv_kernel<<<BB, 128, CHOL_SMEM>>>(Sinv, 256, 65536, W, 256, 65536);
    // V = WA @ Bblk
    gemm_k<128, 128, 0, 0, false><<<dim3(1, 1, BB), 256>>>(128, 128, 128,
        W, 256, 65536,  Sinv + 128, 256, 65536,  nullptr, 0, 0, 1.f,  V, 128, 16384, nullptr);
    cudaEventRecord(evV, 0);

    // s3: X = WA^T @ V  (concurrent with Sc + chol2)
    cudaStreamWaitEvent(s3, evV, 0);
    gemm_k<128, 128, 1, 0, false><<<dim3(1, 1, BB), 256, 0, s3>>>(128, 128, 128,
        W, 256, 65536,  V, 128, 16384,  nullptr, 0, 0, 1.f,  X, 128, 16384, nullptr);
    cudaEventRecord(evX, s3);

    // main: Sc = Dblk - V^T V   (identical to D - B^T A^{-1} B)
    gemm_k<128, 128, 1, 0, false><<<dim3(1, 1, BB), 256>>>(128, 128, 128,
        V, 128, 16384,  V, 128, 16384,
        Sinv + 128 * 256 + 128, 256, 65536, -1.f,  Sc, 128, 16384, nullptr);
    // WS = LSc^{-1} -> W bottom-right
    chol_linv_kernel<<<BB, 128, CHOL_SMEM>>>(Sc, 128, 16384, W + 128 * 256 + 128, 256, 65536);
    // W_BL = -WS @ X^T
    cudaStreamWaitEvent(0, evX, 0);
    gemm_k<128, 128, 0, 1, false><<<dim3(1, 1, BB), 256>>>(128, 128, 128,
        W + 128 * 256 + 128, 256, 65536,  X, 128, 16384,
        nullptr, 0, 0, -1.f,  W + 128 * 256, 256, 65536, nullptr);
    cudaStreamWaitEvent(0, evInit, 0);           // W_TR zeros + spread=1 + acc=0 ready
    cudaEventRecord(evW, 0);                     // W fully assembled

    // s3: spread += rowsq, exploiting W block-lower-triangular structure:
    //   top rows of W*phi use only WA (K=128); bottom rows use [W_BL WS] (K=256)
    cudaStreamWaitEvent(s3, evW, 0);
    gemm_k<128, 128, 0, 1, true><<<dim3(1, 4, BB), 256, 0, s3>>>(512, 128, 128,
        phiQ, 256, 131072,  W, 256, 65536,  nullptr, 0, 0, 1.f,  nullptr, 0, 0, Spr);
    gemm_k<128, 128, 0, 1, true><<<dim3(1, 4, BB), 256, 0, s3>>>(512, 128, 256,
        phiQ, 256, 131072,  W + 128 * 256, 256, 65536,  nullptr, 0, 0, 1.f,  nullptr, 0, 0, Spr);
    cudaEventRecord(evSpr, s3);

    // main (concurrent with spread GEMMs): t = W @ Rhs ; m = W^T t ; mu = phiQ m
    cudaStreamWaitEvent(0, evRhs, 0);
    gemm_k<128, 64, 0, 0, false><<<dim3(1, 2, BB), 256>>>(256, 64, 256,
        W, 256, 65536,  Rhs, 64, 16384,  nullptr, 0, 0, 1.f,  Tt, 64, 16384, nullptr);
    gemm_k<128, 64, 1, 0, false><<<dim3(1, 2, BB), 256>>>(256, 64, 256,
        W, 256, 65536,  Tt, 64, 16384,  nullptr, 0, 0, 1.f,  Mm, 64, 16384, nullptr);
    gemm_k<128, 64, 0, 0, false><<<dim3(1, 4, BB), 256>>>(512, 64, 256,
        phiQ, 256, 131072,  Mm, 64, 16384,  nullptr, 0, 0, 1.f,  mu_out, 64, 32768, nullptr);

    // join: nll needs mu+spread; sig diag needs spread + zero-fill done
    cudaStreamWaitEvent(0, evSpr, 0);
    cudaStreamWaitEvent(0, evZero, 0);
    nll_kernel<<<(BB * NQ) / 256, 256>>>(yQ, mu_out, Spr, se, nacc);
    sigdiag_kernel<<<(BB * NQ * DOUT + 255) / 256, 256>>>(sig_out, Spr, se);
    nll_final_kernel<<<1, 1>>>(nacc, nll_out);

    (void)in_sizes; (void)n_in; (void)out_size;
}